// round 6
// baseline (speedup 1.0000x reference)
#include <cuda_runtime.h>

// Problem shape (fixed by the reference):
//   B = 16384 rows, N = 64 neighbors, D = 64 feat dim, H = 128 outputs
#define BROWS 16384

// Scratch: combined[:,0:128] = [node_f | neigh_agg] per row (hist is read
// directly from its input buffer by the GEMM kernel).
__device__ float g_C[BROWS * 128];
// Pre-transposed classifier weight: g_WT[k*128 + h] = weight[h*256 + k]
__device__ float g_WT[256 * 128];

// ---------------- f32x2 / tanh helpers (sm_103a) ----------------
typedef unsigned long long u64;

__device__ __forceinline__ float tanh_fast(float x) {
    float y; asm("tanh.approx.f32 %0, %1;" : "=f"(y) : "f"(x)); return y;
}
__device__ __forceinline__ u64 pack2(float x) {
    u64 r; asm("mov.b64 %0, {%1, %1};" : "=l"(r) : "f"(x)); return r;
}
__device__ __forceinline__ void fma2(u64& d, u64 a, u64 b) {
    asm("fma.rn.f32x2 %0, %1, %2, %0;" : "+l"(d) : "l"(a), "l"(b));
}
__device__ __forceinline__ float2 unpack2(u64 v) {
    float lo, hi; asm("mov.b64 {%0, %1}, %2;" : "=f"(lo), "=f"(hi) : "l"(v));
    return make_float2(lo, hi);
}

// ---------------- kernel 0: transpose weight [128,256] -> [256,128] --------
__global__ void k_transpose_w(const float* __restrict__ W) {
    int i = blockIdx.x * 256 + threadIdx.x;      // 32768 elements
    int k = i >> 7, h = i & 127;
    g_WT[i] = W[h * 256 + k];
}

// ---------------- kernel 1: per-row features + attention + aggregation -----
// One CTA per row b, 64 threads.
__global__ __launch_bounds__(64)
void k_rows(const float* __restrict__ dt_node, const float* __restrict__ deg_node,
            const float* __restrict__ cc_node, const float* __restrict__ dt_neigh,
            const float* __restrict__ deg_neigh, const float* __restrict__ cc_neigh,
            const unsigned int* __restrict__ mask,  // nonzero == true (f32 or i32 safe)
            const float* __restrict__ t2v_w, const float* __restrict__ t2v_b,
            const float* __restrict__ node_w, const float* __restrict__ node_b,
            const float* __restrict__ W1, const float* __restrict__ W2,
            const float* __restrict__ att_v) {
    __shared__ __align__(16) float sW2[64 * 64];   // att_W2, row-major [d][e]
    __shared__ __align__(16) float sF[64 * 65];    // neighbor features [n][d] (pad 65)
    __shared__ __align__(16) float sA[64];         // (node_f @ W1)[e]
    __shared__ float sNF[64], sV[64];
    __shared__ float sTW[64], sTB[64], sNW[64], sNB[64];
    __shared__ float sWn[64];
    __shared__ float sRed[2];

    const int b = blockIdx.x;
    const int t = threadIdx.x;

    // ---- stage A: stage W2 + parameter vectors into SMEM ----
    {
        const float4* w2v = (const float4*)W2;
        float4* s2v = (float4*)sW2;
#pragma unroll
        for (int i = 0; i < 16; ++i) s2v[t + i * 64] = w2v[t + i * 64];
    }
    float tw = t2v_w[t], tb = t2v_b[t], nw = node_w[t], nb = node_b[t];
    sTW[t] = tw; sTB[t] = tb; sNW[t] = nw; sNB[t] = nb;
    sV[t] = att_v[t];

    // ---- stage B: node feature (thread t == dim d) ----
    float tn = fabsf(dt_node[b]);
    float dcn = deg_node[b] + cc_node[b];
    float v0 = tn * tw + tb;
    float fb = ((t == 0) ? v0 : __cosf(v0)) + dcn * nw + 2.0f * nb;
    float ss = fb * fb;
#pragma unroll
    for (int off = 16; off > 0; off >>= 1) ss += __shfl_xor_sync(0xffffffffu, ss, off);
    if ((t & 31) == 0) sRed[t >> 5] = ss;
    __syncthreads();
    float inv = rsqrtf(fmaxf(sRed[0] + sRed[1], 1e-24f));
    sNF[t] = fb * inv;
    __syncthreads();

    // ---- stage C: a[e] = node_f . W1[:,e] (thread t == e) ----
    {
        float acc = 0.f;
#pragma unroll
        for (int d = 0; d < 64; ++d) acc += sNF[d] * W1[d * 64 + t];
        sA[t] = acc;
    }

    // ---- stage D: neighbor feature (thread t == neighbor n) ----
    const int n = t;
    float dtn = dt_neigh[b * 64 + n];
    float dc = deg_neigh[b * 64 + n] + cc_neigh[b * 64 + n];
    unsigned int mk = mask[b * 64 + n];
    float ta = fabsf(dtn);
    float f[64];
    float ss2 = 0.f;
#pragma unroll
    for (int d = 0; d < 64; ++d) {
        float vv = ta * sTW[d] + sTB[d];
        float c = (d == 0) ? vv : __cosf(vv);
        float val = c + dc * sNW[d] + 2.0f * sNB[d];
        f[d] = val; ss2 += val * val;
    }
    float inv2 = rsqrtf(fmaxf(ss2, 1e-24f));
#pragma unroll
    for (int d = 0; d < 64; ++d) { f[d] *= inv2; sF[n * 65 + d] = f[d]; }

    __syncthreads();  // sA + sF visible

    // ---- stage E: attention  att = sum_e v[e]*tanh(a[e] + f.W2[:,e]) ----
    float att = 0.f;
#pragma unroll
    for (int e0 = 0; e0 < 64; e0 += 8) {
        const ulonglong2* ap = (const ulonglong2*)(sA + e0);
        ulonglong2 a01 = ap[0], a23 = ap[1];
        u64 acc0 = a01.x, acc1 = a01.y, acc2 = a23.x, acc3 = a23.y;
#pragma unroll
        for (int d = 0; d < 64; ++d) {
            u64 fd = pack2(f[d]);
            const ulonglong2* wp = (const ulonglong2*)(sW2 + d * 64 + e0);
            ulonglong2 w01 = wp[0], w23 = wp[1];
            fma2(acc0, fd, w01.x); fma2(acc1, fd, w01.y);
            fma2(acc2, fd, w23.x); fma2(acc3, fd, w23.y);
        }
        float2 p0 = unpack2(acc0), p1 = unpack2(acc1);
        float2 p2 = unpack2(acc2), p3 = unpack2(acc3);
        att += sV[e0 + 0] * tanh_fast(p0.x) + sV[e0 + 1] * tanh_fast(p0.y)
             + sV[e0 + 2] * tanh_fast(p1.x) + sV[e0 + 3] * tanh_fast(p1.y)
             + sV[e0 + 4] * tanh_fast(p2.x) + sV[e0 + 5] * tanh_fast(p2.y)
             + sV[e0 + 6] * tanh_fast(p3.x) + sV[e0 + 7] * tanh_fast(p3.y);
    }

    // ---- score / mask / normalize ----
    float ts = 1.0f / (1.0f + 2.0f * dtn);           // Decayer(2,'rev')
    float ls = (ts > 0.f) ? ts : 0.01f * ts;         // leaky_relu
    float sc = ls * att;
    float mf = mk ? 1.0f : 0.0f;
    float ms = mf;
#pragma unroll
    for (int off = 16; off > 0; off >>= 1) ms += __shfl_xor_sync(0xffffffffu, ms, off);
    if ((t & 31) == 0) sRed[t >> 5] = ms;
    __syncthreads();
    float nin = fmaxf(sRed[0] + sRed[1], 1.0f);
    sWn[n] = mf * sc / nin;
    __syncthreads();

    // ---- stage F: neigh_agg (thread t == dim d) + write combined ----
    {
        const int d = t;
        float agg = 0.f;
#pragma unroll
        for (int m = 0; m < 64; ++m) agg += sWn[m] * sF[m * 65 + d];
        g_C[b * 128 + d] = sNF[d];
        g_C[b * 128 + 64 + d] = agg;
    }
}

// ---------------- kernel 2: out = relu([g_C | hist] @ W^T) ------------------
// M = B, N = 128, K = 256.  BM=64, BN=128, BK=64.  256 threads, 4x8 micro-tile.
__global__ __launch_bounds__(256)
void k_gemm(const float* __restrict__ hist, float* __restrict__ out, int Brows) {
    __shared__ __align__(16) float sAt[64 * 68];   // [row][k] pad 68
    __shared__ __align__(16) float sBt[64 * 128];  // [k][h]
    const int m0 = blockIdx.x * 64;
    const int t = threadIdx.x;
    const int tx = t & 15, ty = t >> 4;
    const int c0 = tx * 8, r0 = ty * 4;

    u64 acc[4][4];
#pragma unroll
    for (int j = 0; j < 4; ++j)
#pragma unroll
        for (int p = 0; p < 4; ++p) acc[j][p] = 0ull;

    for (int k0 = 0; k0 < 256; k0 += 64) {
        __syncthreads();
        // load A tile (first 128 k from g_C, last 128 from hist)
        const float* src = (k0 < 128) ? g_C : hist;
        const int koff = (k0 < 128) ? k0 : (k0 - 128);
#pragma unroll
        for (int i = 0; i < 4; ++i) {
            int s = t + i * 256;              // 1024 float4 slots
            int r = s >> 4, k4 = (s & 15) * 4;
            float4 vv = *(const float4*)(src + (m0 + r) * 128 + koff + k4);
            *(float4*)(sAt + r * 68 + k4) = vv;
        }
        // load B tile from pre-transposed weight (coalesced)
#pragma unroll
        for (int i = 0; i < 8; ++i) {
            int s = t + i * 256;              // 2048 float4 slots
            int kk = s >> 5, h4 = (s & 31) * 4;
            *(float4*)(sBt + kk * 128 + h4) =
                *(const float4*)(g_WT + (k0 + kk) * 128 + h4);
        }
        __syncthreads();
#pragma unroll 8
        for (int kk = 0; kk < 64; ++kk) {
            const ulonglong2* bp = (const ulonglong2*)(sBt + kk * 128 + c0);
            ulonglong2 b01 = bp[0], b23 = bp[1];
#pragma unroll
            for (int j = 0; j < 4; ++j) {
                u64 a2 = pack2(sAt[(r0 + j) * 68 + kk]);
                fma2(acc[j][0], a2, b01.x); fma2(acc[j][1], a2, b01.y);
                fma2(acc[j][2], a2, b23.x); fma2(acc[j][3], a2, b23.y);
            }
        }
    }
#pragma unroll
    for (int j = 0; j < 4; ++j) {
        float2 p0 = unpack2(acc[j][0]), p1 = unpack2(acc[j][1]);
        float2 p2 = unpack2(acc[j][2]), p3 = unpack2(acc[j][3]);
        float4 lo = make_float4(fmaxf(p0.x, 0.f), fmaxf(p0.y, 0.f),
                                fmaxf(p1.x, 0.f), fmaxf(p1.y, 0.f));
        float4 hi = make_float4(fmaxf(p2.x, 0.f), fmaxf(p2.y, 0.f),
                                fmaxf(p3.x, 0.f), fmaxf(p3.y, 0.f));
        int row = m0 + r0 + j;
        if (row < Brows) {
            *(float4*)(out + row * 128 + c0) = lo;
            *(float4*)(out + row * 128 + c0 + 4) = hi;
        }
    }
}

// ---------------------------- launcher --------------------------------------
extern "C" void kernel_launch(void* const* d_in, const int* in_sizes, int n_in,
                              void* d_out, int out_size) {
    const float* dt_node   = (const float*)d_in[0];
    const float* deg_node  = (const float*)d_in[1];
    const float* cc_node   = (const float*)d_in[2];
    const float* dt_neigh  = (const float*)d_in[3];
    const float* deg_neigh = (const float*)d_in[4];
    const float* cc_neigh  = (const float*)d_in[5];
    const unsigned int* mask = (const unsigned int*)d_in[6];
    const float* hist      = (const float*)d_in[7];
    const float* t2v_w     = (const float*)d_in[8];
    const float* t2v_b     = (const float*)d_in[9];
    const float* node_w    = (const float*)d_in[10];
    const float* node_b    = (const float*)d_in[11];
    const float* att_W1    = (const float*)d_in[12];
    const float* att_W2    = (const float*)d_in[13];
    const float* att_v     = (const float*)d_in[14];
    const float* weight    = (const float*)d_in[15];
    float* out = (float*)d_out;

    const int B = in_sizes[0];   // 16384

    k_transpose_w<<<128, 256>>>(weight);
    k_rows<<<B, 64>>>(dt_node, deg_node, cc_node, dt_neigh, deg_neigh, cc_neigh,
                      mask, t2v_w, t2v_b, node_w, node_b, att_W1, att_W2, att_v);
    k_gemm<<<(B + 63) / 64, 256>>>(hist, out, B);
}

// round 8
// speedup vs baseline: 2.3090x; 2.3090x over previous
#include <cuda_runtime.h>

// Problem shape: B = 16384 rows, N = 64 neighbors, D = 64, H = 128
#define BROWS 16384

__device__ float g_C[BROWS * 128];     // [node_f | neigh_agg] per row
__device__ float g_WT[256 * 128];      // transposed classifier weight

typedef unsigned long long u64;
typedef unsigned int u32;

// ---------------- helpers ----------------
__device__ __forceinline__ float tanh_fast(float x) {
    float y; asm("tanh.approx.f32 %0, %1;" : "=f"(y) : "f"(x)); return y;
}
__device__ __forceinline__ u64 pack2(float x) {
    u64 r; asm("mov.b64 %0, {%1, %1};" : "=l"(r) : "f"(x)); return r;
}
__device__ __forceinline__ void fma2(u64& d, u64 a, u64 b) {
    asm("fma.rn.f32x2 %0, %1, %2, %0;" : "+l"(d) : "l"(a), "l"(b));
}
__device__ __forceinline__ float2 unpack2(u64 v) {
    float lo, hi; asm("mov.b64 {%0, %1}, %2;" : "=f"(lo), "=f"(hi) : "l"(v));
    return make_float2(lo, hi);
}
__device__ __forceinline__ u32 to_tf32(float x) {
    u32 r; asm("cvt.rna.tf32.f32 %0, %1;" : "=r"(r) : "f"(x)); return r;
}
// m16n8k8 tf32 MMA: D = A(16x8,row) * B(8x8,col) + D, fp32 accum
__device__ __forceinline__ void mma8(float* c, const u32* a, u32 b0, u32 b1) {
    asm("mma.sync.aligned.m16n8k8.row.col.f32.tf32.tf32.f32 "
        "{%0,%1,%2,%3}, {%4,%5,%6,%7}, {%8,%9}, {%0,%1,%2,%3};"
        : "+f"(c[0]), "+f"(c[1]), "+f"(c[2]), "+f"(c[3])
        : "r"(a[0]), "r"(a[1]), "r"(a[2]), "r"(a[3]), "r"(b0), "r"(b1));
}

// ---------------- SMEM layout (dynamic, bytes) ----------------
// F tiles: 2 rows x [64 neighbors x pitch 68 floats]  (pitch 68 : 68 mod 32 = 4
//   -> conflict-free A-fragment LDS, balanced float4 stores)
#define FPITCH      68
#define OFF_F       0                         // 2*64*68*4 = 34816
#define OFF_BF      34816                     // W2 B-fragments: 64 tiles*32*8 = 16384
#define OFF_W1      51200                     // 16384
#define OFF_NF      67584                     // 512  node_f [2][64]
#define OFF_AE      68096                     // 512  a = node_f@W1 [2][64]
#define OFF_ATT     68608                     // 512  att [2][64]
#define OFF_WN      69120                     // 512  w_n [2][64]
#define OFF_V       69632                     // 256
#define OFF_TW      69888
#define OFF_TB      70144
#define OFF_NW      70400
#define OFF_NB      70656
#define OFF_RED     70912                     // 32
#define SMEM_TOTAL  71168

// ---------------- kernel 0: transpose weight [128,256] -> [256,128] --------
__global__ void k_transpose_w(const float* __restrict__ W) {
    int i = blockIdx.x * 256 + threadIdx.x;
    int k = i >> 7, h = i & 127;
    g_WT[i] = W[h * 256 + k];
}

// ---------------- kernel 1: persistent, 2 rows/iter, mma.sync tf32 ---------
__global__ __launch_bounds__(128, 3)
void k_rows(const float* __restrict__ dt_node, const float* __restrict__ deg_node,
            const float* __restrict__ cc_node, const float* __restrict__ dt_neigh,
            const float* __restrict__ deg_neigh, const float* __restrict__ cc_neigh,
            const unsigned int* __restrict__ mask,
            const float* __restrict__ t2v_w, const float* __restrict__ t2v_b,
            const float* __restrict__ node_w, const float* __restrict__ node_b,
            const float* __restrict__ W1, const float* __restrict__ W2,
            const float* __restrict__ att_v, int pairs) {
    extern __shared__ __align__(16) char sm[];
    float* sF  = (float*)(sm + OFF_F);
    float2* sBF = (float2*)(sm + OFF_BF);
    float* sW1 = (float*)(sm + OFF_W1);
    float* sNF = (float*)(sm + OFF_NF);
    float* sAE = (float*)(sm + OFF_AE);
    float* sAtt = (float*)(sm + OFF_ATT);
    float* sWn = (float*)(sm + OFF_WN);
    float* sV  = (float*)(sm + OFF_V);
    float* sTW = (float*)(sm + OFF_TW);
    float* sTB = (float*)(sm + OFF_TB);
    float* sNW = (float*)(sm + OFF_NW);
    float* sNB = (float*)(sm + OFF_NB);
    float* sRed = (float*)(sm + OFF_RED);

    const int t = threadIdx.x;
    const int lane = t & 31, wid = t >> 5;
    const int row = t >> 6;        // which row of the pair (feature stages)
    const int dn  = t & 63;        // dim / neighbor index (feature stages)
    // MMA-stage mapping: warp -> (row, neighbor half)
    const int mrow = wid >> 1, mhalf = wid & 1;
    const int g = lane >> 2, tq = lane & 3;

    // ---- one-time init ----
    {   // W1 plain [d][e]
        const float4* src = (const float4*)W1;
        float4* dst = (float4*)sW1;
#pragma unroll
        for (int i = 0; i < 8; ++i) dst[t + i * 128] = src[t + i * 128];
    }
    // W2 -> B fragments (tf32): tile (kt,nt): b0=W2[kt*8+tq][nt*8+g], b1=+4 row
#pragma unroll
    for (int i = 0; i < 16; ++i) {
        int tile = wid * 16 + i;
        int kt = tile >> 3, nt = tile & 7;
        int d = kt * 8 + tq, e = nt * 8 + g;
        float2 v;
        v.x = __uint_as_float(to_tf32(W2[d * 64 + e]));
        v.y = __uint_as_float(to_tf32(W2[(d + 4) * 64 + e]));
        sBF[tile * 32 + lane] = v;
    }
    if (t < 64) { sV[t] = att_v[t]; sTW[t] = t2v_w[t]; sTB[t] = t2v_b[t];
                  sNW[t] = node_w[t]; sNB[t] = node_b[t]; }
    __syncthreads();

    for (int p = blockIdx.x; p < pairs; p += gridDim.x) {
        const int b = p * 2 + row;

        // ---- node feature partial: thread (row, d=dn) ----
        float tn  = fabsf(dt_node[b]);
        float dcn = deg_node[b] + cc_node[b];
        float vv0 = tn * sTW[dn] + sTB[dn];
        float fb  = ((dn == 0) ? vv0 : __cosf(vv0)) + dcn * sNW[dn] + 2.0f * sNB[dn];
        float ss = fb * fb;
#pragma unroll
        for (int off = 16; off > 0; off >>= 1) ss += __shfl_xor_sync(0xffffffffu, ss, off);
        if (lane == 0) sRed[wid] = ss;
        __syncthreads();                                   // (A)
        float inv = rsqrtf(fmaxf(sRed[row * 2] + sRed[row * 2 + 1], 1e-24f));
        sNF[t] = fb * inv;

        // ---- neighbor feature: thread (row, n=dn) -> sF (tf32-rounded) ----
        float dtn = dt_neigh[b * 64 + dn];
        float dc  = deg_neigh[b * 64 + dn] + cc_neigh[b * 64 + dn];
        unsigned int mk = mask[b * 64 + dn];
        {
            float ta = fabsf(dtn);
            float f[64]; float s2 = 0.f;
#pragma unroll
            for (int d = 0; d < 64; ++d) {
                float vv = ta * sTW[d] + sTB[d];
                float cv = (d == 0) ? vv : __cosf(vv);
                float val = cv + dc * sNW[d] + 2.0f * sNB[d];
                f[d] = val; s2 += val * val;
            }
            float inv2 = rsqrtf(fmaxf(s2, 1e-24f));
            float* frow = sF + (row * 64 + dn) * FPITCH;
#pragma unroll
            for (int q = 0; q < 16; ++q) {
                float4 v4;
                v4.x = __uint_as_float(to_tf32(f[4 * q + 0] * inv2));
                v4.y = __uint_as_float(to_tf32(f[4 * q + 1] * inv2));
                v4.z = __uint_as_float(to_tf32(f[4 * q + 2] * inv2));
                v4.w = __uint_as_float(to_tf32(f[4 * q + 3] * inv2));
                *(float4*)(frow + 4 * q) = v4;
            }
        }
        __syncthreads();                                   // (B) sNF+sF visible

        // ---- a[e] = node_f . W1[:,e]: thread (row, e=dn) ----
        {
            float acc = 0.f;
#pragma unroll
            for (int d = 0; d < 64; ++d) acc += sNF[row * 64 + d] * sW1[d * 64 + dn];
            sAE[t] = acc;
        }
        __syncthreads();                                   // (C) sAE visible

        // ---- MMA: warp covers 32 neighbors (2 M-tiles) x 64 e x 64 d ----
        float cacc[2][8][4];
#pragma unroll
        for (int mt = 0; mt < 2; ++mt)
#pragma unroll
            for (int nt = 0; nt < 8; ++nt)
#pragma unroll
                for (int c = 0; c < 4; ++c) cacc[mt][nt][c] = 0.f;

        const float* fbase = sF + (mrow * 64 + mhalf * 32) * FPITCH;
#pragma unroll
        for (int kt = 0; kt < 8; ++kt) {
            u32 a[2][4];
#pragma unroll
            for (int mt = 0; mt < 2; ++mt) {
                const float* ap = fbase + mt * 16 * FPITCH + kt * 8;
                a[mt][0] = __float_as_uint(ap[g * FPITCH + tq]);
                a[mt][1] = __float_as_uint(ap[(g + 8) * FPITCH + tq]);
                a[mt][2] = __float_as_uint(ap[g * FPITCH + tq + 4]);
                a[mt][3] = __float_as_uint(ap[(g + 8) * FPITCH + tq + 4]);
            }
#pragma unroll
            for (int nt = 0; nt < 8; ++nt) {
                float2 bb = sBF[(kt * 8 + nt) * 32 + lane];
                u32 b0 = __float_as_uint(bb.x), b1 = __float_as_uint(bb.y);
                mma8(cacc[0][nt], a[0], b0, b1);
                mma8(cacc[1][nt], a[1], b0, b1);
            }
        }

        // ---- epilogue: att = sum_e v[e]*tanh(a[e] + proj[n][e]) ----
        {
            const float* aE = sAE + mrow * 64;
            float attv[2][2] = {{0.f, 0.f}, {0.f, 0.f}};   // [mt][row g / g+8]
#pragma unroll
            for (int nt = 0; nt < 8; ++nt) {
                float v0 = sV[nt * 8 + 2 * tq], v1 = sV[nt * 8 + 2 * tq + 1];
                float a0 = aE[nt * 8 + 2 * tq], a1 = aE[nt * 8 + 2 * tq + 1];
#pragma unroll
                for (int mt = 0; mt < 2; ++mt) {
                    attv[mt][0] += v0 * tanh_fast(a0 + cacc[mt][nt][0])
                                 + v1 * tanh_fast(a1 + cacc[mt][nt][1]);
                    attv[mt][1] += v0 * tanh_fast(a0 + cacc[mt][nt][2])
                                 + v1 * tanh_fast(a1 + cacc[mt][nt][3]);
                }
            }
#pragma unroll
            for (int mt = 0; mt < 2; ++mt)
#pragma unroll
                for (int r2 = 0; r2 < 2; ++r2) {
                    float x = attv[mt][r2];
                    x += __shfl_xor_sync(0xffffffffu, x, 1);
                    x += __shfl_xor_sync(0xffffffffu, x, 2);
                    if (tq == 0)
                        sAtt[mrow * 64 + mhalf * 32 + mt * 16 + r2 * 8 + g] = x;
                }
        }
        __syncthreads();                                   // (D) sAtt visible

        // ---- score / mask / normalize: thread (row, n=dn) ----
        float at = sAtt[t];
        float ts = 1.0f / (1.0f + 2.0f * dtn);             // Decayer(2,'rev')
        float ls = (ts > 0.f) ? ts : 0.01f * ts;           // leaky_relu
        float sc = ls * at;
        float mf = mk ? 1.0f : 0.0f;
        float ms = mf;
#pragma unroll
        for (int off = 16; off > 0; off >>= 1) ms += __shfl_xor_sync(0xffffffffu, ms, off);
        if (lane == 0) sRed[wid] = ms;
        __syncthreads();                                   // (E0)
        float nin = fmaxf(sRed[row * 2] + sRed[row * 2 + 1], 1.0f);
        sWn[t] = mf * sc / nin;
        __syncthreads();                                   // (E)

        // ---- aggregation: thread (row, d=dn) ----
        {
            float ag = 0.f;
            const float* fr = sF + row * 64 * FPITCH;
#pragma unroll
            for (int n = 0; n < 64; ++n) ag += sWn[row * 64 + n] * fr[n * FPITCH + dn];
            g_C[b * 128 + dn] = sNF[t];
            g_C[b * 128 + 64 + dn] = ag;
        }
        __syncthreads();                                   // top guard for sF reuse
    }
}

// ---------------- kernel 2: out = relu([g_C | hist] @ W^T) ------------------
__global__ __launch_bounds__(256)
void k_gemm(const float* __restrict__ hist, float* __restrict__ out, int Brows) {
    __shared__ __align__(16) float sAt[64 * 68];
    __shared__ __align__(16) float sBt[64 * 128];
    const int m0 = blockIdx.x * 64;
    const int t = threadIdx.x;
    const int tx = t & 15, ty = t >> 4;
    const int c0 = tx * 8, r0 = ty * 4;

    u64 acc[4][4];
#pragma unroll
    for (int j = 0; j < 4; ++j)
#pragma unroll
        for (int pq = 0; pq < 4; ++pq) acc[j][pq] = 0ull;

    for (int k0 = 0; k0 < 256; k0 += 64) {
        __syncthreads();
        const float* src = (k0 < 128) ? g_C : hist;
        const int koff = (k0 < 128) ? k0 : (k0 - 128);
#pragma unroll
        for (int i = 0; i < 4; ++i) {
            int s = t + i * 256;
            int r = s >> 4, k4 = (s & 15) * 4;
            float4 vv = *(const float4*)(src + (m0 + r) * 128 + koff + k4);
            *(float4*)(sAt + r * 68 + k4) = vv;
        }
#pragma unroll
        for (int i = 0; i < 8; ++i) {
            int s = t + i * 256;
            int kk = s >> 5, h4 = (s & 31) * 4;
            *(float4*)(sBt + kk * 128 + h4) =
                *(const float4*)(g_WT + (k0 + kk) * 128 + h4);
        }
        __syncthreads();
#pragma unroll 8
        for (int kk = 0; kk < 64; ++kk) {
            const ulonglong2* bp = (const ulonglong2*)(sBt + kk * 128 + c0);
            ulonglong2 b01 = bp[0], b23 = bp[1];
#pragma unroll
            for (int j = 0; j < 4; ++j) {
                u64 a2 = pack2(sAt[(r0 + j) * 68 + kk]);
                fma2(acc[j][0], a2, b01.x); fma2(acc[j][1], a2, b01.y);
                fma2(acc[j][2], a2, b23.x); fma2(acc[j][3], a2, b23.y);
            }
        }
    }
#pragma unroll
    for (int j = 0; j < 4; ++j) {
        float2 p0 = unpack2(acc[j][0]), p1 = unpack2(acc[j][1]);
        float2 p2 = unpack2(acc[j][2]), p3 = unpack2(acc[j][3]);
        float4 lo = make_float4(fmaxf(p0.x, 0.f), fmaxf(p0.y, 0.f),
                                fmaxf(p1.x, 0.f), fmaxf(p1.y, 0.f));
        float4 hi = make_float4(fmaxf(p2.x, 0.f), fmaxf(p2.y, 0.f),
                                fmaxf(p3.x, 0.f), fmaxf(p3.y, 0.f));
        int rrow = m0 + r0 + j;
        if (rrow < Brows) {
            *(float4*)(out + rrow * 128 + c0) = lo;
            *(float4*)(out + rrow * 128 + c0 + 4) = hi;
        }
    }
}

// ---------------------------- launcher --------------------------------------
extern "C" void kernel_launch(void* const* d_in, const int* in_sizes, int n_in,
                              void* d_out, int out_size) {
    const float* dt_node   = (const float*)d_in[0];
    const float* deg_node  = (const float*)d_in[1];
    const float* cc_node   = (const float*)d_in[2];
    const float* dt_neigh  = (const float*)d_in[3];
    const float* deg_neigh = (const float*)d_in[4];
    const float* cc_neigh  = (const float*)d_in[5];
    const unsigned int* mask = (const unsigned int*)d_in[6];
    const float* hist      = (const float*)d_in[7];
    const float* t2v_w     = (const float*)d_in[8];
    const float* t2v_b     = (const float*)d_in[9];
    const float* node_w    = (const float*)d_in[10];
    const float* node_b    = (const float*)d_in[11];
    const float* att_W1    = (const float*)d_in[12];
    const float* att_W2    = (const float*)d_in[13];
    const float* att_v     = (const float*)d_in[14];
    const float* weight    = (const float*)d_in[15];
    float* out = (float*)d_out;

    const int B = in_sizes[0];   // 16384
    const int pairs = B / 2;

    static int smem_set = 0;
    if (!smem_set) {
        cudaFuncSetAttribute(k_rows, cudaFuncAttributeMaxDynamicSharedMemorySize,
                             SMEM_TOTAL);
        smem_set = 1;
    }

    k_transpose_w<<<128, 256>>>(weight);
    k_rows<<<444, 128, SMEM_TOTAL>>>(dt_node, deg_node, cc_node, dt_neigh,
                                     deg_neigh, cc_neigh, mask, t2v_w, t2v_b,
                                     node_w, node_b, att_W1, att_W2, att_v,
                                     pairs);
    k_gemm<<<(B + 63) / 64, 256>>>(hist, out, B);
}

// round 9
// speedup vs baseline: 2.4071x; 1.0425x over previous
#include <cuda_runtime.h>

// Problem shape: B = 16384 rows, N = 64 neighbors, D = 64, H = 128
#define BROWS 16384

__device__ float g_C[BROWS * 128];     // [node_f | neigh_agg] per row
__device__ float g_WT[256 * 128];      // transposed classifier weight

typedef unsigned long long u64;
typedef unsigned int u32;

// ---------------- helpers ----------------
__device__ __forceinline__ float tanh_fast(float x) {
    float y; asm("tanh.approx.f32 %0, %1;" : "=f"(y) : "f"(x)); return y;
}
__device__ __forceinline__ u64 pack2(float x) {
    u64 r; asm("mov.b64 %0, {%1, %1};" : "=l"(r) : "f"(x)); return r;
}
__device__ __forceinline__ void fma2(u64& d, u64 a, u64 b) {
    asm("fma.rn.f32x2 %0, %1, %2, %0;" : "+l"(d) : "l"(a), "l"(b));
}
__device__ __forceinline__ float2 unpack2(u64 v) {
    float lo, hi; asm("mov.b64 {%0, %1}, %2;" : "=f"(lo), "=f"(hi) : "l"(v));
    return make_float2(lo, hi);
}
__device__ __forceinline__ u32 to_tf32(float x) {
    u32 r; asm("cvt.rna.tf32.f32 %0, %1;" : "=r"(r) : "f"(x)); return r;
}
// m16n8k8 tf32 MMA: D = A(16x8,row) * B(8x8,col) + D, fp32 accum
__device__ __forceinline__ void mma8(float* c, const u32* a, u32 b0, u32 b1) {
    asm("mma.sync.aligned.m16n8k8.row.col.f32.tf32.tf32.f32 "
        "{%0,%1,%2,%3}, {%4,%5,%6,%7}, {%8,%9}, {%0,%1,%2,%3};"
        : "+f"(c[0]), "+f"(c[1]), "+f"(c[2]), "+f"(c[3])
        : "r"(a[0]), "r"(a[1]), "r"(a[2]), "r"(a[3]), "r"(b0), "r"(b1));
}
// row-group barrier: syncs only the 2 warps owning `row` (ids 1 and 2)
__device__ __forceinline__ void bar_row(int row) {
    asm volatile("bar.sync %0, 64;" :: "r"(row + 1) : "memory");
}

// ---------------- SMEM layout (dynamic, bytes) ----------------
// F tiles: 2 rows x [64 neighbors x pitch 68 floats]
#define FPITCH      68
#define OFF_F       0                         // 2*64*68*4 = 34816
#define OFF_BF      34816                     // W2 B-fragments: 64 tiles*32*8 = 16384
#define OFF_W1      51200                     // 16384
#define OFF_NF      67584                     // 512  node_f [2][64]
#define OFF_AE      68096                     // 512  a = node_f@W1 [2][64]
#define OFF_ATT     68608                     // 512  att [2][64]
#define OFF_WN      69120                     // 512  w_n [2][64]
#define OFF_V       69632                     // 256
#define OFF_TW      69888
#define OFF_TB      70144
#define OFF_NW      70400
#define OFF_NB      70656
#define OFF_RED     70912                     // 64 (norm[4] + mask[4])
#define SMEM_TOTAL  71168

// ---------------- kernel 1: persistent, 2 independent row pipelines --------
__global__ __launch_bounds__(128, 3)
void k_rows(const float* __restrict__ dt_node, const float* __restrict__ deg_node,
            const float* __restrict__ cc_node, const float* __restrict__ dt_neigh,
            const float* __restrict__ deg_neigh, const float* __restrict__ cc_neigh,
            const unsigned int* __restrict__ mask,
            const float* __restrict__ t2v_w, const float* __restrict__ t2v_b,
            const float* __restrict__ node_w, const float* __restrict__ node_b,
            const float* __restrict__ W1, const float* __restrict__ W2,
            const float* __restrict__ att_v, const float* __restrict__ Wcls,
            int pairs) {
    extern __shared__ __align__(16) char sm[];
    float* sF  = (float*)(sm + OFF_F);
    float2* sBF = (float2*)(sm + OFF_BF);
    float* sW1 = (float*)(sm + OFF_W1);
    float* sNF = (float*)(sm + OFF_NF);
    float* sAE = (float*)(sm + OFF_AE);
    float* sAtt = (float*)(sm + OFF_ATT);
    float* sWn = (float*)(sm + OFF_WN);
    float* sV  = (float*)(sm + OFF_V);
    float* sTW = (float*)(sm + OFF_TW);
    float* sTB = (float*)(sm + OFF_TB);
    float* sNW = (float*)(sm + OFF_NW);
    float* sNB = (float*)(sm + OFF_NB);
    float* sRedN = (float*)(sm + OFF_RED);       // [4] norm partials
    float* sRedM = (float*)(sm + OFF_RED) + 4;   // [4] mask-count partials

    const int t = threadIdx.x;
    const int lane = t & 31, wid = t >> 5;
    const int row = t >> 6;        // which row of the pair (0/1)
    const int dn  = t & 63;        // dim / neighbor index
    // MMA mapping: warps {2r,2r+1} own row r; within, half = wid&1
    const int mrow = wid >> 1, mhalf = wid & 1;
    const int g = lane >> 2, tq = lane & 3;

    // ---- fold-in: transpose classifier weight (runs once, before pair loop)
    for (int i = blockIdx.x * 128 + t; i < 256 * 128; i += gridDim.x * 128) {
        int k = i >> 7, h = i & 127;
        g_WT[i] = Wcls[h * 256 + k];
    }

    // ---- one-time init ----
    {   // W1 plain [d][e]
        const float4* src = (const float4*)W1;
        float4* dst = (float4*)sW1;
#pragma unroll
        for (int i = 0; i < 8; ++i) dst[t + i * 128] = src[t + i * 128];
    }
    // W2 -> B fragments (tf32)
#pragma unroll
    for (int i = 0; i < 16; ++i) {
        int tile = wid * 16 + i;
        int kt = tile >> 3, nt = tile & 7;
        int d = kt * 8 + tq, e = nt * 8 + g;
        float2 v;
        v.x = __uint_as_float(to_tf32(W2[d * 64 + e]));
        v.y = __uint_as_float(to_tf32(W2[(d + 4) * 64 + e]));
        sBF[tile * 32 + lane] = v;
    }
    if (t < 64) { sV[t] = att_v[t]; sTW[t] = t2v_w[t]; sTB[t] = t2v_b[t];
                  sNW[t] = node_w[t]; sNB[t] = node_b[t]; }
    __syncthreads();

    // ---- prefetch first iteration's inputs ----
    int p = blockIdx.x;
    float pv_tn = 0.f, pv_dcn = 0.f, pv_dtn = 0.f, pv_dc = 0.f;
    u32 pv_mk = 0;
    {
        int b = p * 2 + row;
        pv_tn  = fabsf(dt_node[b]);
        pv_dcn = deg_node[b] + cc_node[b];
        pv_dtn = dt_neigh[b * 64 + dn];
        pv_dc  = deg_neigh[b * 64 + dn] + cc_neigh[b * 64 + dn];
        pv_mk  = mask[b * 64 + dn];
    }

    for (; p < pairs; p += gridDim.x) {
        const int b = p * 2 + row;
        const float c_tn = pv_tn, c_dcn = pv_dcn;
        const float c_dtn = pv_dtn, c_dc = pv_dc;
        const u32 c_mk = pv_mk;

        // ---- node feature partial + mask count: thread (row, d=dn) ----
        float vv0 = c_tn * sTW[dn] + sTB[dn];
        float fb  = ((dn == 0) ? vv0 : __cosf(vv0)) + c_dcn * sNW[dn] + 2.0f * sNB[dn];
        float ss = fb * fb;
        float ms = c_mk ? 1.0f : 0.0f;
        const float mf = ms;
#pragma unroll
        for (int off = 16; off > 0; off >>= 1) {
            ss += __shfl_xor_sync(0xffffffffu, ss, off);
            ms += __shfl_xor_sync(0xffffffffu, ms, off);
        }
        if (lane == 0) { sRedN[wid] = ss; sRedM[wid] = ms; }
        bar_row(row);                                      // (A) + sF/sNF guard
        float inv = rsqrtf(fmaxf(sRedN[row * 2] + sRedN[row * 2 + 1], 1e-24f));
        const float nin = fmaxf(sRedM[row * 2] + sRedM[row * 2 + 1], 1.0f);
        sNF[t] = fb * inv;

        // ---- neighbor feature: thread (row, n=dn) -> sF (tf32-rounded) ----
        {
            float ta = fabsf(c_dtn);
            float f[64]; float s2 = 0.f;
#pragma unroll
            for (int d = 0; d < 64; ++d) {
                float vv = ta * sTW[d] + sTB[d];
                float cv = (d == 0) ? vv : __cosf(vv);
                float val = cv + c_dc * sNW[d] + 2.0f * sNB[d];
                f[d] = val; s2 += val * val;
            }
            float inv2 = rsqrtf(fmaxf(s2, 1e-24f));
            float* frow = sF + (row * 64 + dn) * FPITCH;
#pragma unroll
            for (int q = 0; q < 16; ++q) {
                float4 v4;
                v4.x = __uint_as_float(to_tf32(f[4 * q + 0] * inv2));
                v4.y = __uint_as_float(to_tf32(f[4 * q + 1] * inv2));
                v4.z = __uint_as_float(to_tf32(f[4 * q + 2] * inv2));
                v4.w = __uint_as_float(to_tf32(f[4 * q + 3] * inv2));
                *(float4*)(frow + 4 * q) = v4;
            }
        }
        bar_row(row);                                      // (B) sNF+sF visible

        // ---- prefetch next iteration (hidden under aE + MMA + epilogue) ----
        {
            int pn = p + gridDim.x;
            if (pn < pairs) {
                int bn = pn * 2 + row;
                pv_tn  = fabsf(dt_node[bn]);
                pv_dcn = deg_node[bn] + cc_node[bn];
                pv_dtn = dt_neigh[bn * 64 + dn];
                pv_dc  = deg_neigh[bn * 64 + dn] + cc_neigh[bn * 64 + dn];
                pv_mk  = mask[bn * 64 + dn];
            }
        }

        // ---- a[e] = node_f . W1[:,e]: thread (row, e=dn) ----
        {
            float acc = 0.f;
#pragma unroll
            for (int d = 0; d < 64; ++d) acc += sNF[row * 64 + d] * sW1[d * 64 + dn];
            sAE[t] = acc;
        }
        bar_row(row);                                      // (C) sAE visible

        // ---- MMA: warp covers 32 neighbors (2 M-tiles) x 64 e x 64 d ----
        float cacc[2][8][4];
#pragma unroll
        for (int mt = 0; mt < 2; ++mt)
#pragma unroll
            for (int nt = 0; nt < 8; ++nt)
#pragma unroll
                for (int c = 0; c < 4; ++c) cacc[mt][nt][c] = 0.f;

        const float* fbase = sF + (mrow * 64 + mhalf * 32) * FPITCH;
#pragma unroll
        for (int kt = 0; kt < 8; ++kt) {
            u32 a[2][4];
#pragma unroll
            for (int mt = 0; mt < 2; ++mt) {
                const float* ap = fbase + mt * 16 * FPITCH + kt * 8;
                a[mt][0] = __float_as_uint(ap[g * FPITCH + tq]);
                a[mt][1] = __float_as_uint(ap[(g + 8) * FPITCH + tq]);
                a[mt][2] = __float_as_uint(ap[g * FPITCH + tq + 4]);
                a[mt][3] = __float_as_uint(ap[(g + 8) * FPITCH + tq + 4]);
            }
#pragma unroll
            for (int nt = 0; nt < 8; ++nt) {
                float2 bb = sBF[(kt * 8 + nt) * 32 + lane];
                u32 b0 = __float_as_uint(bb.x), b1 = __float_as_uint(bb.y);
                mma8(cacc[0][nt], a[0], b0, b1);
                mma8(cacc[1][nt], a[1], b0, b1);
            }
        }

        // ---- epilogue: att = sum_e v[e]*tanh(a[e] + proj[n][e]) ----
        {
            const float* aE = sAE + mrow * 64;
            float attv[2][2] = {{0.f, 0.f}, {0.f, 0.f}};
#pragma unroll
            for (int nt = 0; nt < 8; ++nt) {
                float v0 = sV[nt * 8 + 2 * tq], v1 = sV[nt * 8 + 2 * tq + 1];
                float a0 = aE[nt * 8 + 2 * tq], a1 = aE[nt * 8 + 2 * tq + 1];
#pragma unroll
                for (int mt = 0; mt < 2; ++mt) {
                    attv[mt][0] += v0 * tanh_fast(a0 + cacc[mt][nt][0])
                                 + v1 * tanh_fast(a1 + cacc[mt][nt][1]);
                    attv[mt][1] += v0 * tanh_fast(a0 + cacc[mt][nt][2])
                                 + v1 * tanh_fast(a1 + cacc[mt][nt][3]);
                }
            }
#pragma unroll
            for (int mt = 0; mt < 2; ++mt)
#pragma unroll
                for (int r2 = 0; r2 < 2; ++r2) {
                    float x = attv[mt][r2];
                    x += __shfl_xor_sync(0xffffffffu, x, 1);
                    x += __shfl_xor_sync(0xffffffffu, x, 2);
                    if (tq == 0)
                        sAtt[mrow * 64 + mhalf * 32 + mt * 16 + r2 * 8 + g] = x;
                }
        }
        bar_row(row);                                      // (D) sAtt visible

        // ---- score / mask / normalize: thread (row, n=dn) ----
        float at = sAtt[t];
        float ts = 1.0f / (1.0f + 2.0f * c_dtn);           // Decayer(2,'rev')
        float ls = (ts > 0.f) ? ts : 0.01f * ts;           // leaky_relu
        sWn[t] = mf * (ls * at) / nin;
        bar_row(row);                                      // (E) sWn visible

        // ---- aggregation: thread (row, d=dn) ----
        {
            float ag = 0.f;
            const float* fr = sF + row * 64 * FPITCH;
#pragma unroll
            for (int n = 0; n < 64; ++n) ag += sWn[row * 64 + n] * fr[n * FPITCH + dn];
            g_C[b * 128 + dn] = sNF[t];
            g_C[b * 128 + 64 + dn] = ag;
        }
        // barrier (A) of the next iteration guards sF/sNF/sWn reuse
    }
}

// ---------------- kernel 2: out = relu([g_C | hist] @ W^T) ------------------
__global__ __launch_bounds__(256)
void k_gemm(const float* __restrict__ hist, float* __restrict__ out, int Brows) {
    __shared__ __align__(16) float sAt[64 * 68];
    __shared__ __align__(16) float sBt[64 * 128];
    const int m0 = blockIdx.x * 64;
    const int t = threadIdx.x;
    const int tx = t & 15, ty = t >> 4;
    const int c0 = tx * 8, r0 = ty * 4;

    u64 acc[4][4];
#pragma unroll
    for (int j = 0; j < 4; ++j)
#pragma unroll
        for (int pq = 0; pq < 4; ++pq) acc[j][pq] = 0ull;

    for (int k0 = 0; k0 < 256; k0 += 64) {
        __syncthreads();
        const float* src = (k0 < 128) ? g_C : hist;
        const int koff = (k0 < 128) ? k0 : (k0 - 128);
#pragma unroll
        for (int i = 0; i < 4; ++i) {
            int s = t + i * 256;
            int r = s >> 4, k4 = (s & 15) * 4;
            float4 vv = *(const float4*)(src + (m0 + r) * 128 + koff + k4);
            *(float4*)(sAt + r * 68 + k4) = vv;
        }
#pragma unroll
        for (int i = 0; i < 8; ++i) {
            int s = t + i * 256;
            int kk = s >> 5, h4 = (s & 31) * 4;
            *(float4*)(sBt + kk * 128 + h4) =
                *(const float4*)(g_WT + (k0 + kk) * 128 + h4);
        }
        __syncthreads();
#pragma unroll 8
        for (int kk = 0; kk < 64; ++kk) {
            const ulonglong2* bp = (const ulonglong2*)(sBt + kk * 128 + c0);
            ulonglong2 b01 = bp[0], b23 = bp[1];
#pragma unroll
            for (int j = 0; j < 4; ++j) {
                u64 a2 = pack2(sAt[(r0 + j) * 68 + kk]);
                fma2(acc[j][0], a2, b01.x); fma2(acc[j][1], a2, b01.y);
                fma2(acc[j][2], a2, b23.x); fma2(acc[j][3], a2, b23.y);
            }
        }
    }
#pragma unroll
    for (int j = 0; j < 4; ++j) {
        float2 p0 = unpack2(acc[j][0]), p1 = unpack2(acc[j][1]);
        float2 p2 = unpack2(acc[j][2]), p3 = unpack2(acc[j][3]);
        float4 lo = make_float4(fmaxf(p0.x, 0.f), fmaxf(p0.y, 0.f),
                                fmaxf(p1.x, 0.f), fmaxf(p1.y, 0.f));
        float4 hi = make_float4(fmaxf(p2.x, 0.f), fmaxf(p2.y, 0.f),
                                fmaxf(p3.x, 0.f), fmaxf(p3.y, 0.f));
        int rrow = m0 + r0 + j;
        if (rrow < Brows) {
            *(float4*)(out + rrow * 128 + c0) = lo;
            *(float4*)(out + rrow * 128 + c0 + 4) = hi;
        }
    }
}

// ---------------------------- launcher --------------------------------------
extern "C" void kernel_launch(void* const* d_in, const int* in_sizes, int n_in,
                              void* d_out, int out_size) {
    const float* dt_node   = (const float*)d_in[0];
    const float* deg_node  = (const float*)d_in[1];
    const float* cc_node   = (const float*)d_in[2];
    const float* dt_neigh  = (const float*)d_in[3];
    const float* deg_neigh = (const float*)d_in[4];
    const float* cc_neigh  = (const float*)d_in[5];
    const unsigned int* mask = (const unsigned int*)d_in[6];
    const float* hist      = (const float*)d_in[7];
    const float* t2v_w     = (const float*)d_in[8];
    const float* t2v_b     = (const float*)d_in[9];
    const float* node_w    = (const float*)d_in[10];
    const float* node_b    = (const float*)d_in[11];
    const float* att_W1    = (const float*)d_in[12];
    const float* att_W2    = (const float*)d_in[13];
    const float* att_v     = (const float*)d_in[14];
    const float* weight    = (const float*)d_in[15];
    float* out = (float*)d_out;

    const int B = in_sizes[0];   // 16384
    const int pairs = B / 2;

    static int smem_set = 0;
    if (!smem_set) {
        cudaFuncSetAttribute(k_rows, cudaFuncAttributeMaxDynamicSharedMemorySize,
                             SMEM_TOTAL);
        smem_set = 1;
    }

    k_rows<<<444, 128, SMEM_TOTAL>>>(dt_node, deg_node, cc_node, dt_neigh,
                                     deg_neigh, cc_neigh, mask, t2v_w, t2v_b,
                                     node_w, node_b, att_W1, att_W2, att_v,
                                     weight, pairs);
    k_gemm<<<(B + 63) / 64, 256>>>(hist, out, B);
}

// round 10
// speedup vs baseline: 3.1173x; 1.2950x over previous
#include <cuda_runtime.h>

// Problem shape: B = 16384 rows, N = 64 neighbors, D = 64, H = 128
#define BROWS 16384

__device__ float g_C[BROWS * 128];     // [node_f | neigh_agg] per row
// Classifier weight pre-converted to tf32 B-fragment layout:
// tile (kt 0..31, nt 0..15), lane 0..31 (g=lane>>2, tq=lane&3):
//   .x = tf32(W[h=nt*8+g][k=kt*8+tq]),  .y = tf32(W[h][k+4])
__device__ float2 g_WF[512 * 32];

typedef unsigned long long u64;
typedef unsigned int u32;

// ---------------- helpers ----------------
__device__ __forceinline__ float tanh_fast(float x) {
    float y; asm("tanh.approx.f32 %0, %1;" : "=f"(y) : "f"(x)); return y;
}
__device__ __forceinline__ u32 to_tf32(float x) {
    u32 r; asm("cvt.rna.tf32.f32 %0, %1;" : "=r"(r) : "f"(x)); return r;
}
// m16n8k8 tf32 MMA: D = A(16x8,row) * B(8x8,col) + D, fp32 accum
__device__ __forceinline__ void mma8(float* c, const u32* a, u32 b0, u32 b1) {
    asm("mma.sync.aligned.m16n8k8.row.col.f32.tf32.tf32.f32 "
        "{%0,%1,%2,%3}, {%4,%5,%6,%7}, {%8,%9}, {%0,%1,%2,%3};"
        : "+f"(c[0]), "+f"(c[1]), "+f"(c[2]), "+f"(c[3])
        : "r"(a[0]), "r"(a[1]), "r"(a[2]), "r"(a[3]), "r"(b0), "r"(b1));
}
// row-group barrier: syncs only the 2 warps owning `row`
__device__ __forceinline__ void bar_row(int row) {
    asm volatile("bar.sync %0, 64;" :: "r"(row + 1) : "memory");
}

// ---------------- SMEM layout for k_rows (dynamic, bytes) ----------------
#define FPITCH      68
#define OFF_F       0                         // 2*64*68*4 = 34816
#define OFF_BF      34816                     // W2 B-fragments: 64 tiles*32*8 = 16384
#define OFF_W1      51200                     // 16384
#define OFF_NF      67584                     // 512  node_f [2][64]
#define OFF_AE      68096                     // 512  a = node_f@W1 [2][64]
#define OFF_ATT     68608                     // 512  att [2][64]
#define OFF_WN      69120                     // 512  w_n [2][64]
#define OFF_V       69632                     // 256
#define OFF_TW      69888
#define OFF_TB      70144
#define OFF_NW      70400
#define OFF_NB      70656
#define OFF_RED     70912                     // 64 (norm[4] + mask[4])
#define SMEM_TOTAL  71168

// SMEM for k_gemm: A tile [128][68] floats + B fragments 4096 float2
#define GEMM_SMEM   (128 * 68 * 4 + 4096 * 8)   // 34816 + 32768 = 67584

// ---------------- kernel 1: persistent, 2 independent row pipelines --------
__global__ __launch_bounds__(128, 3)
void k_rows(const float* __restrict__ dt_node, const float* __restrict__ deg_node,
            const float* __restrict__ cc_node, const float* __restrict__ dt_neigh,
            const float* __restrict__ deg_neigh, const float* __restrict__ cc_neigh,
            const unsigned int* __restrict__ mask,
            const float* __restrict__ t2v_w, const float* __restrict__ t2v_b,
            const float* __restrict__ node_w, const float* __restrict__ node_b,
            const float* __restrict__ W1, const float* __restrict__ W2,
            const float* __restrict__ att_v, const float* __restrict__ Wcls,
            int pairs) {
    extern __shared__ __align__(16) char sm[];
    float* sF  = (float*)(sm + OFF_F);
    float2* sBF = (float2*)(sm + OFF_BF);
    float* sW1 = (float*)(sm + OFF_W1);
    float* sNF = (float*)(sm + OFF_NF);
    float* sAE = (float*)(sm + OFF_AE);
    float* sAtt = (float*)(sm + OFF_ATT);
    float* sWn = (float*)(sm + OFF_WN);
    float* sV  = (float*)(sm + OFF_V);
    float* sTW = (float*)(sm + OFF_TW);
    float* sTB = (float*)(sm + OFF_TB);
    float* sNW = (float*)(sm + OFF_NW);
    float* sNB = (float*)(sm + OFF_NB);
    float* sRedN = (float*)(sm + OFF_RED);       // [4] norm partials
    float* sRedM = (float*)(sm + OFF_RED) + 4;   // [4] mask-count partials

    const int t = threadIdx.x;
    const int lane = t & 31, wid = t >> 5;
    const int row = t >> 6;        // which row of the pair (0/1)
    const int dn  = t & 63;        // dim / neighbor index
    const int mrow = wid >> 1, mhalf = wid & 1;
    const int g = lane >> 2, tq = lane & 3;

    // ---- fold-in: classifier weight -> tf32 B-fragment layout (once) ----
    for (int e = blockIdx.x * 128 + t; e < 512 * 32; e += gridDim.x * 128) {
        int tile = e >> 5, ln = e & 31;
        int kt = tile >> 4, nt = tile & 15;
        int gg = ln >> 2, tqq = ln & 3;
        const float* wr = Wcls + (nt * 8 + gg) * 256 + kt * 8 + tqq;
        float2 v;
        v.x = __uint_as_float(to_tf32(wr[0]));
        v.y = __uint_as_float(to_tf32(wr[4]));
        g_WF[e] = v;
    }

    // ---- one-time init ----
    {   // W1 plain [d][e]
        const float4* src = (const float4*)W1;
        float4* dst = (float4*)sW1;
#pragma unroll
        for (int i = 0; i < 8; ++i) dst[t + i * 128] = src[t + i * 128];
    }
    // W2 -> B fragments (tf32)
#pragma unroll
    for (int i = 0; i < 16; ++i) {
        int tile = wid * 16 + i;
        int kt = tile >> 3, nt = tile & 7;
        int d = kt * 8 + tq, e = nt * 8 + g;
        float2 v;
        v.x = __uint_as_float(to_tf32(W2[d * 64 + e]));
        v.y = __uint_as_float(to_tf32(W2[(d + 4) * 64 + e]));
        sBF[tile * 32 + lane] = v;
    }
    if (t < 64) { sV[t] = att_v[t]; sTW[t] = t2v_w[t]; sTB[t] = t2v_b[t];
                  sNW[t] = node_w[t]; sNB[t] = node_b[t]; }
    __syncthreads();

    // ---- prefetch first iteration's inputs ----
    int p = blockIdx.x;
    float pv_tn = 0.f, pv_dcn = 0.f, pv_dtn = 0.f, pv_dc = 0.f;
    u32 pv_mk = 0;
    {
        int b = p * 2 + row;
        pv_tn  = fabsf(dt_node[b]);
        pv_dcn = deg_node[b] + cc_node[b];
        pv_dtn = dt_neigh[b * 64 + dn];
        pv_dc  = deg_neigh[b * 64 + dn] + cc_neigh[b * 64 + dn];
        pv_mk  = mask[b * 64 + dn];
    }

    for (; p < pairs; p += gridDim.x) {
        const int b = p * 2 + row;
        const float c_tn = pv_tn, c_dcn = pv_dcn;
        const float c_dtn = pv_dtn, c_dc = pv_dc;
        const u32 c_mk = pv_mk;

        // ---- node feature partial + mask count: thread (row, d=dn) ----
        float vv0 = c_tn * sTW[dn] + sTB[dn];
        float fb  = ((dn == 0) ? vv0 : __cosf(vv0)) + c_dcn * sNW[dn] + 2.0f * sNB[dn];
        float ss = fb * fb;
        float ms = c_mk ? 1.0f : 0.0f;
        const float mf = ms;
#pragma unroll
        for (int off = 16; off > 0; off >>= 1) {
            ss += __shfl_xor_sync(0xffffffffu, ss, off);
            ms += __shfl_xor_sync(0xffffffffu, ms, off);
        }
        if (lane == 0) { sRedN[wid] = ss; sRedM[wid] = ms; }
        bar_row(row);                                      // (A) + sF/sNF guard
        float inv = rsqrtf(fmaxf(sRedN[row * 2] + sRedN[row * 2 + 1], 1e-24f));
        const float nin = fmaxf(sRedM[row * 2] + sRedM[row * 2 + 1], 1.0f);
        sNF[t] = fb * inv;

        // ---- neighbor feature: thread (row, n=dn) -> sF (tf32-rounded) ----
        {
            float ta = fabsf(c_dtn);
            float f[64]; float s2 = 0.f;
#pragma unroll
            for (int d = 0; d < 64; ++d) {
                float vv = ta * sTW[d] + sTB[d];
                float cv = (d == 0) ? vv : __cosf(vv);
                float val = cv + c_dc * sNW[d] + 2.0f * sNB[d];
                f[d] = val; s2 += val * val;
            }
            float inv2 = rsqrtf(fmaxf(s2, 1e-24f));
            float* frow = sF + (row * 64 + dn) * FPITCH;
#pragma unroll
            for (int q = 0; q < 16; ++q) {
                float4 v4;
                v4.x = __uint_as_float(to_tf32(f[4 * q + 0] * inv2));
                v4.y = __uint_as_float(to_tf32(f[4 * q + 1] * inv2));
                v4.z = __uint_as_float(to_tf32(f[4 * q + 2] * inv2));
                v4.w = __uint_as_float(to_tf32(f[4 * q + 3] * inv2));
                *(float4*)(frow + 4 * q) = v4;
            }
        }
        bar_row(row);                                      // (B) sNF+sF visible

        // ---- prefetch next iteration ----
        {
            int pn = p + gridDim.x;
            if (pn < pairs) {
                int bn = pn * 2 + row;
                pv_tn  = fabsf(dt_node[bn]);
                pv_dcn = deg_node[bn] + cc_node[bn];
                pv_dtn = dt_neigh[bn * 64 + dn];
                pv_dc  = deg_neigh[bn * 64 + dn] + cc_neigh[bn * 64 + dn];
                pv_mk  = mask[bn * 64 + dn];
            }
        }

        // ---- a[e] = node_f . W1[:,e]: thread (row, e=dn) ----
        {
            float acc = 0.f;
#pragma unroll
            for (int d = 0; d < 64; ++d) acc += sNF[row * 64 + d] * sW1[d * 64 + dn];
            sAE[t] = acc;
        }
        bar_row(row);                                      // (C) sAE visible

        // ---- MMA: warp covers 32 neighbors (2 M-tiles) x 64 e x 64 d ----
        float cacc[2][8][4];
#pragma unroll
        for (int mt = 0; mt < 2; ++mt)
#pragma unroll
            for (int nt = 0; nt < 8; ++nt)
#pragma unroll
                for (int c = 0; c < 4; ++c) cacc[mt][nt][c] = 0.f;

        const float* fbase = sF + (mrow * 64 + mhalf * 32) * FPITCH;
#pragma unroll
        for (int kt = 0; kt < 8; ++kt) {
            u32 a[2][4];
#pragma unroll
            for (int mt = 0; mt < 2; ++mt) {
                const float* ap = fbase + mt * 16 * FPITCH + kt * 8;
                a[mt][0] = __float_as_uint(ap[g * FPITCH + tq]);
                a[mt][1] = __float_as_uint(ap[(g + 8) * FPITCH + tq]);
                a[mt][2] = __float_as_uint(ap[g * FPITCH + tq + 4]);
                a[mt][3] = __float_as_uint(ap[(g + 8) * FPITCH + tq + 4]);
            }
#pragma unroll
            for (int nt = 0; nt < 8; ++nt) {
                float2 bb = sBF[(kt * 8 + nt) * 32 + lane];
                u32 b0 = __float_as_uint(bb.x), b1 = __float_as_uint(bb.y);
                mma8(cacc[0][nt], a[0], b0, b1);
                mma8(cacc[1][nt], a[1], b0, b1);
            }
        }

        // ---- epilogue: att = sum_e v[e]*tanh(a[e] + proj[n][e]) ----
        {
            const float* aE = sAE + mrow * 64;
            float attv[2][2] = {{0.f, 0.f}, {0.f, 0.f}};
#pragma unroll
            for (int nt = 0; nt < 8; ++nt) {
                float v0 = sV[nt * 8 + 2 * tq], v1 = sV[nt * 8 + 2 * tq + 1];
                float a0 = aE[nt * 8 + 2 * tq], a1 = aE[nt * 8 + 2 * tq + 1];
#pragma unroll
                for (int mt = 0; mt < 2; ++mt) {
                    attv[mt][0] += v0 * tanh_fast(a0 + cacc[mt][nt][0])
                                 + v1 * tanh_fast(a1 + cacc[mt][nt][1]);
                    attv[mt][1] += v0 * tanh_fast(a0 + cacc[mt][nt][2])
                                 + v1 * tanh_fast(a1 + cacc[mt][nt][3]);
                }
            }
#pragma unroll
            for (int mt = 0; mt < 2; ++mt)
#pragma unroll
                for (int r2 = 0; r2 < 2; ++r2) {
                    float x = attv[mt][r2];
                    x += __shfl_xor_sync(0xffffffffu, x, 1);
                    x += __shfl_xor_sync(0xffffffffu, x, 2);
                    if (tq == 0)
                        sAtt[mrow * 64 + mhalf * 32 + mt * 16 + r2 * 8 + g] = x;
                }
        }
        bar_row(row);                                      // (D) sAtt visible

        // ---- score / mask / normalize: thread (row, n=dn) ----
        float at = sAtt[t];
        float ts = 1.0f / (1.0f + 2.0f * c_dtn);           // Decayer(2,'rev')
        float ls = (ts > 0.f) ? ts : 0.01f * ts;           // leaky_relu
        sWn[t] = mf * (ls * at) / nin;
        bar_row(row);                                      // (E) sWn visible

        // ---- aggregation: thread (row, d=dn) ----
        {
            float ag = 0.f;
            const float* fr = sF + row * 64 * FPITCH;
#pragma unroll
            for (int n = 0; n < 64; ++n) ag += sWn[row * 64 + n] * fr[n * FPITCH + dn];
            g_C[b * 128 + dn] = sNF[t];
            g_C[b * 128 + 64 + dn] = ag;
        }
        // barrier (A) of next iteration guards sF/sNF/sWn reuse
    }
}

// ---------------- kernel 2: out = relu([g_C | hist] @ W^T), tf32 MMA -------
// M=16384, N=128, K=256. CTA tile 128x128, BK=64, 256 threads (8 warps).
// Warp w: rows (w>>1)*32..+32, cols (w&1)*64..+64 -> 2 Mtiles x 8 Ntiles.
__global__ __launch_bounds__(256)
void k_gemm(const float* __restrict__ hist, float* __restrict__ out) {
    extern __shared__ __align__(16) float sg[];
    float* sA = sg;                         // [128][68]
    float2* sB = (float2*)(sg + 128 * 68);  // 128 tiles * 32 lanes per K-block

    const int m0 = blockIdx.x * 128;
    const int t = threadIdx.x;
    const int lane = t & 31, wid = t >> 5;
    const int mrow = wid >> 1, nhalf = wid & 1;
    const int g = lane >> 2, tq = lane & 3;

    float acc[2][8][4];
#pragma unroll
    for (int mt = 0; mt < 2; ++mt)
#pragma unroll
        for (int nt = 0; nt < 8; ++nt)
#pragma unroll
            for (int c = 0; c < 4; ++c) acc[mt][nt][c] = 0.f;

#pragma unroll
    for (int kb = 0; kb < 4; ++kb) {
        const float* src = (kb < 2) ? g_C : hist;
        const int koff = (kb & 1) * 64;
        __syncthreads();
        // stage A: 128 rows x 64 cols, tf32-rounded, pitch 68
#pragma unroll
        for (int i = 0; i < 8; ++i) {
            int s = t + i * 256;
            int r = s >> 4, k4 = (s & 15) * 4;
            float4 v = *(const float4*)(src + (m0 + r) * 128 + koff + k4);
            float4 w;
            w.x = __uint_as_float(to_tf32(v.x));
            w.y = __uint_as_float(to_tf32(v.y));
            w.z = __uint_as_float(to_tf32(v.z));
            w.w = __uint_as_float(to_tf32(v.w));
            *(float4*)(sA + r * 68 + k4) = w;
        }
        // stage B fragments: contiguous 32KB copy (tiles kb*8..kb*8+7, all nt)
        {
            const float4* wf = (const float4*)(g_WF + kb * 8 * 16 * 32);
            float4* sb4 = (float4*)sB;
#pragma unroll
            for (int i = 0; i < 8; ++i) sb4[t + i * 256] = wf[t + i * 256];
        }
        __syncthreads();

#pragma unroll
        for (int ktl = 0; ktl < 8; ++ktl) {
            u32 a[2][4];
#pragma unroll
            for (int mt = 0; mt < 2; ++mt) {
                const float* ap = sA + (mrow * 32 + mt * 16) * 68 + ktl * 8;
                a[mt][0] = __float_as_uint(ap[g * 68 + tq]);
                a[mt][1] = __float_as_uint(ap[(g + 8) * 68 + tq]);
                a[mt][2] = __float_as_uint(ap[g * 68 + tq + 4]);
                a[mt][3] = __float_as_uint(ap[(g + 8) * 68 + tq + 4]);
            }
#pragma unroll
            for (int nt = 0; nt < 8; ++nt) {
                float2 bb = sB[(ktl * 16 + nhalf * 8 + nt) * 32 + lane];
                u32 b0 = __float_as_uint(bb.x), b1 = __float_as_uint(bb.y);
                mma8(acc[0][nt], a[0], b0, b1);
                mma8(acc[1][nt], a[1], b0, b1);
            }
        }
    }

    // epilogue: relu + store (float2 per fragment pair)
#pragma unroll
    for (int mt = 0; mt < 2; ++mt) {
#pragma unroll
        for (int nt = 0; nt < 8; ++nt) {
            int r1 = m0 + mrow * 32 + mt * 16 + g;
            int cc = nhalf * 64 + nt * 8 + 2 * tq;
            float2 lo, hi;
            lo.x = fmaxf(acc[mt][nt][0], 0.f);
            lo.y = fmaxf(acc[mt][nt][1], 0.f);
            hi.x = fmaxf(acc[mt][nt][2], 0.f);
            hi.y = fmaxf(acc[mt][nt][3], 0.f);
            *(float2*)(out + r1 * 128 + cc) = lo;
            *(float2*)(out + (r1 + 8) * 128 + cc) = hi;
        }
    }
}

// ---------------------------- launcher --------------------------------------
extern "C" void kernel_launch(void* const* d_in, const int* in_sizes, int n_in,
                              void* d_out, int out_size) {
    const float* dt_node   = (const float*)d_in[0];
    const float* deg_node  = (const float*)d_in[1];
    const float* cc_node   = (const float*)d_in[2];
    const float* dt_neigh  = (const float*)d_in[3];
    const float* deg_neigh = (const float*)d_in[4];
    const float* cc_neigh  = (const float*)d_in[5];
    const unsigned int* mask = (const unsigned int*)d_in[6];
    const float* hist      = (const float*)d_in[7];
    const float* t2v_w     = (const float*)d_in[8];
    const float* t2v_b     = (const float*)d_in[9];
    const float* node_w    = (const float*)d_in[10];
    const float* node_b    = (const float*)d_in[11];
    const float* att_W1    = (const float*)d_in[12];
    const float* att_W2    = (const float*)d_in[13];
    const float* att_v     = (const float*)d_in[14];
    const float* weight    = (const float*)d_in[15];
    float* out = (float*)d_out;

    const int B = in_sizes[0];   // 16384
    const int pairs = B / 2;

    static int smem_set = 0;
    if (!smem_set) {
        cudaFuncSetAttribute(k_rows, cudaFuncAttributeMaxDynamicSharedMemorySize,
                             SMEM_TOTAL);
        cudaFuncSetAttribute(k_gemm, cudaFuncAttributeMaxDynamicSharedMemorySize,
                             GEMM_SMEM);
        smem_set = 1;
    }

    k_rows<<<444, 128, SMEM_TOTAL>>>(dt_node, deg_node, cc_node, dt_neigh,
                                     deg_neigh, cc_neigh, mask, t2v_w, t2v_b,
                                     node_w, node_b, att_W1, att_W2, att_v,
                                     weight, pairs);
    k_gemm<<<B / 128, 256, GEMM_SMEM>>>(hist, out);
}